// round 10
// baseline (speedup 1.0000x reference)
#include <cuda_runtime.h>
#include <cstdint>
#include <math.h>

#define BB 8192
#define KD 256     // complex dim K
#define MD 1024    // sparse dim M
#define TT 10

#define PLB 16384                    // plane bytes: 128 rows x 128B (32 floats, no pad; XOR swizzle)
#define STGB (3 * PLB)               // stage: A-hi, A-lo, X (49152 B)
#define SMEM_BYTES (2 * STGB)        // 98304 B

// ---------------- scratch ----------------
__device__ __align__(16) float g_x[BB * 512];          // x    [b][2K]
__device__ __align__(16) float g_xmap[BB * 512];       // xmap [b][2K]
__device__ __align__(16) float g_b0[BB * 512];         // b0   [b][2K]
__device__ __align__(16) float g_xsp[(size_t)BB * MD]; // xsp  [b][M]
__device__ __align__(16) float g_Rh[512 * 512],  g_Rl[512 * 512];
__device__ __align__(16) float g_Wh[512 * 256],  g_Wl[512 * 256];
__device__ __align__(16) float g_Eh[MD * 512],   g_El[MD * 512];
__device__ __align__(16) float g_Dh[512 * MD],   g_Dl[512 * MD];
__device__ __align__(16) float g_acc[3];

// ---------------- asm helpers ----------------
__device__ __forceinline__ uint32_t smem_u32(const void* p) {
    uint32_t a;
    asm("{ .reg .u64 t; cvta.to.shared.u64 t, %1; cvt.u32.u64 %0, t; }" : "=r"(a) : "l"(p));
    return a;
}
__device__ __forceinline__ void cp16(uint32_t dst, const void* src) {
    asm volatile("cp.async.cg.shared.global [%0], [%1], 16;" :: "r"(dst), "l"(src));
}
__device__ __forceinline__ void cp_commit() {
    asm volatile("cp.async.commit_group;" ::: "memory");
}
template <int N>
__device__ __forceinline__ void cp_wait() {
    asm volatile("cp.async.wait_group %0;" :: "n"(N) : "memory");
}
__device__ __forceinline__ float4 lds128(uint32_t addr) {
    float4 v;
    asm volatile("ld.shared.v4.f32 {%0,%1,%2,%3}, [%4];"
                 : "=f"(v.x), "=f"(v.y), "=f"(v.z), "=f"(v.w) : "r"(addr));
    return v;
}
__device__ __forceinline__ void mma8(float* c, uint32_t a0, uint32_t a1, uint32_t a2, uint32_t a3,
                                     uint32_t b0, uint32_t b1) {
    asm volatile(
        "mma.sync.aligned.m16n8k8.row.col.f32.tf32.tf32.f32 "
        "{%0,%1,%2,%3}, {%4,%5,%6,%7}, {%8,%9}, {%0,%1,%2,%3};"
        : "+f"(c[0]), "+f"(c[1]), "+f"(c[2]), "+f"(c[3])
        : "r"(a0), "r"(a1), "r"(a2), "r"(a3), "r"(b0), "r"(b1));
}
// hi = tf32-rounded v (as fp32); lo = raw residual (tf32 MMA truncates its tail; ~2^-21, negligible)
__device__ __forceinline__ void splitw(float v, float& h, float& l) {
    uint32_t hb;
    asm("cvt.rna.tf32.f32 %0, %1;" : "=r"(hb) : "f"(v));
    h = __uint_as_float(hb);
    l = v - h;
}
__device__ __forceinline__ float tf32r(float v) {
    uint32_t hb;
    asm("cvt.rna.tf32.f32 %0, %1;" : "=r"(hb) : "f"(v));
    return __uint_as_float(hb);
}
#define U(x) __float_as_uint(x)

// ---------------- tensor-core GEMM: D[m][b] = A[m][:] . X[b][:] ----------------
// A pre-split into (hi, lo) fp32 planes; X raw fp32, split in-loop.
// EPI: 0 = plain store, 1 = x-update, 2 = shrink(+L1,+count), 3 = xmap(+huber)
template <int KIN, int MOUT, int EPI>
__global__ void __launch_bounds__(256, 2) k_gemm(
    const float* __restrict__ Ahi, const float* __restrict__ Alo,
    const float* __restrict__ Xm, float* __restrict__ OUT,
    const float* __restrict__ aux1, const float* __restrict__ aux2,
    const float* __restrict__ scal, int last)
{
    extern __shared__ __align__(16) char smraw[];
    const uint32_t sb = smem_u32(smraw);
    const int tid = threadIdx.x;
    const int wid = tid >> 5, lane = tid & 31;
    const int g = lane >> 2, tg = lane & 3;
    const int bb0 = blockIdx.x * 128;
    const int m0 = blockIdx.y * 128;
    const int m_off = (wid & 1) * 64;
    const int n_off = (wid >> 1) * 32;

    constexpr int NS = KIN / 32;

    // issue stage st -> buf st&1 (swizzled: chunk c of row r stored at c ^ ((r&1)<<2))
    auto issue = [&](int st) {
        const int kk = st * 32;
        const uint32_t base = sb + (uint32_t)(st & 1) * STGB;
#pragma unroll
        for (int k4 = 0; k4 < 4; k4++) {
            int q = tid + 256 * k4;           // 0..1023
            int row = q >> 3, cc = q & 7;
            uint32_t sw = (uint32_t)(cc ^ ((row & 1) << 2));
            uint32_t doff = (uint32_t)(row * 128) + sw * 16;
            size_t asrc = (size_t)(m0 + row) * KIN + kk + cc * 4;
            size_t xsrc = (size_t)(bb0 + row) * KIN + kk + cc * 4;
            cp16(base + doff,            Ahi + asrc);
            cp16(base + PLB + doff,      Alo + asrc);
            cp16(base + 2 * PLB + doff,  Xm + xsrc);
        }
        cp_commit();
    };

    float c[4][4][4];
#pragma unroll
    for (int i = 0; i < 4; i++)
#pragma unroll
        for (int j = 0; j < 4; j++)
#pragma unroll
            for (int q = 0; q < 4; q++) c[i][j][q] = 0.f;

    issue(0);
    issue(1);

    for (int kt = 0; kt < NS; kt++) {
        cp_wait<1>();
        __syncthreads();
        const uint32_t Ahb = sb + (uint32_t)(kt & 1) * STGB;
        const uint32_t Alb = Ahb + PLB;
        const uint32_t Xb  = Ahb + 2 * PLB;
#pragma unroll
        for (int ksp = 0; ksp < 2; ksp++) {
            const int cbase = ksp * 4 + tg;
            // X fragments: one LDS.128 per nf covers 2 MMA k-steps (k-permuted)
            float4 xh[4], xl[4];
#pragma unroll
            for (int nf = 0; nf < 4; nf++) {
                int r = n_off + nf * 8 + g;
                uint32_t ad = Xb + (uint32_t)(r * 128) + (uint32_t)((cbase ^ ((r & 1) << 2)) * 16);
                float4 xv = lds128(ad);
                splitw(xv.x, xh[nf].x, xl[nf].x);
                splitw(xv.y, xh[nf].y, xl[nf].y);
                splitw(xv.z, xh[nf].z, xl[nf].z);
                splitw(xv.w, xh[nf].w, xl[nf].w);
            }
#pragma unroll
            for (int mf = 0; mf < 4; mf++) {
                int r0 = m_off + mf * 16 + g;
                int r1 = r0 + 8;                 // same parity as r0 -> same swizzle
                uint32_t co = (uint32_t)((cbase ^ ((r0 & 1) << 2)) * 16);
                float4 h0 = lds128(Ahb + (uint32_t)(r0 * 128) + co);
                float4 h1 = lds128(Ahb + (uint32_t)(r1 * 128) + co);
                float4 l0 = lds128(Alb + (uint32_t)(r0 * 128) + co);
                float4 l1 = lds128(Alb + (uint32_t)(r1 * 128) + co);
#pragma unroll
                for (int nf = 0; nf < 4; nf++) {
                    // k-step s=0 (elements .x/.y)
                    mma8(c[mf][nf], U(h0.x), U(h1.x), U(h0.y), U(h1.y), U(xh[nf].x), U(xh[nf].y));
                    mma8(c[mf][nf], U(h0.x), U(h1.x), U(h0.y), U(h1.y), U(xl[nf].x), U(xl[nf].y));
                    mma8(c[mf][nf], U(l0.x), U(l1.x), U(l0.y), U(l1.y), U(xh[nf].x), U(xh[nf].y));
                    // k-step s=1 (elements .z/.w)
                    mma8(c[mf][nf], U(h0.z), U(h1.z), U(h0.w), U(h1.w), U(xh[nf].z), U(xh[nf].w));
                    mma8(c[mf][nf], U(h0.z), U(h1.z), U(h0.w), U(h1.w), U(xl[nf].z), U(xl[nf].w));
                    mma8(c[mf][nf], U(l0.z), U(l1.z), U(l0.w), U(l1.w), U(xh[nf].z), U(xh[nf].w));
                }
            }
        }
        __syncthreads();
        if (kt + 2 < NS) issue(kt + 2);
        else cp_commit();            // keep group count aligned for cp_wait<1>
    }

    // ---------------- epilogue ----------------
    float s_a = 0.f, s_b = 0.f;
    float gam = 0.f, eta = 0.f;
    if (EPI == 1) gam = scal[0];
    if (EPI == 2) eta = scal[0];
#pragma unroll
    for (int mf = 0; mf < 4; mf++)
#pragma unroll
        for (int nf = 0; nf < 4; nf++) {
#pragma unroll
            for (int q = 0; q < 4; q++) {
                int m = m0 + m_off + mf * 16 + g + (q >= 2 ? 8 : 0);
                int b = bb0 + n_off + nf * 8 + tg * 2 + (q & 1);
                size_t o = (size_t)b * MOUT + m;
                float d = c[mf][nf][q];
                if (EPI == 0) {
                    OUT[o] = d;
                } else if (EPI == 1) {
                    OUT[o] = aux1[o] - gam * (d - aux2[o]);
                } else if (EPI == 2) {
                    float ad = fabsf(d) - eta;
                    float v = (ad > 0.f) ? copysignf(ad, d) : 0.f;
                    OUT[o] = v;
                    s_a += fabsf(v);
                    if (last) s_b += (fabsf(v) > 1e-3f) ? 1.f : 0.f;
                } else {
                    float xo = aux1[o];
                    float dd = xo - d; float ad = fabsf(dd);
                    s_a += (ad < 1.f) ? 0.5f * dd * dd : ad - 0.5f;
                    OUT[o] = d;
                }
            }
        }
    if (EPI == 2 || EPI == 3) {
#pragma unroll
        for (int off = 16; off > 0; off >>= 1) {
            s_a += __shfl_down_sync(0xffffffffu, s_a, off);
            if (EPI == 2) s_b += __shfl_down_sync(0xffffffffu, s_b, off);
        }
        if (lane == 0) {
            atomicAdd(&g_acc[EPI == 2 ? 0 : 1], s_a);
            if (EPI == 2 && last) atomicAdd(&g_acc[2], s_b);
        }
    }
}

// ---------------- prep kernels ----------------
__global__ void k_zero() { if (threadIdx.x < 3) g_acc[threadIdx.x] = 0.f; }

// R = real form of P = WX(2,256,128) @ W(2,128,256); write hi/lo planes
__global__ void k_prep_R(const float* __restrict__ W, const float* __restrict__ WX) {
    int j = blockIdx.x * 16 + threadIdx.x;   // 0..255
    int i = blockIdx.y * 16 + threadIdx.y;   // 0..255
    float pre = 0.f, pim = 0.f;
#pragma unroll 4
    for (int n = 0; n < 128; n++) {
        float ar = WX[i * 128 + n], ai = WX[32768 + i * 128 + n];
        float br = W[n * 256 + j],  bi = W[32768 + n * 256 + j];
        pre += ar * br - ai * bi;
        pim += ar * bi + ai * br;
    }
    float h, l;
    splitw(pre, h, l);  g_Rh[i * 512 + j] = h;               g_Rl[i * 512 + j] = l;
    splitw(-pim, h, l); g_Rh[i * 512 + j + 256] = h;         g_Rl[i * 512 + j + 256] = l;
    splitw(pim, h, l);  g_Rh[(i + 256) * 512 + j] = h;       g_Rl[(i + 256) * 512 + j] = l;
    splitw(pre, h, l);  g_Rh[(i + 256) * 512 + j + 256] = h; g_Rl[(i + 256) * 512 + j + 256] = l;
}

// WXr / E / D hi,lo planes in one grid-stride kernel
__global__ void k_prepB(const float* __restrict__ E0, const float* __restrict__ WX) {
    size_t idx = (size_t)blockIdx.x * 256 + threadIdx.x;
    float h, l;
    if (idx < 131072) {                           // WXr [512][256]
        int np = (int)idx & 255, j = (int)idx >> 8;
        int jj = j & 255, jr = j >> 8;
        int nn = np & 127, nc = np >> 7;
        float re = WX[jj * 128 + nn], im = WX[32768 + jj * 128 + nn];
        float v = (jr == 0) ? ((nc == 0) ? re : -im) : ((nc == 0) ? im : re);
        splitw(v, h, l); g_Wh[idx] = h; g_Wl[idx] = l;
    } else if (idx < 131072 + 524288) {           // E [1024][512]
        size_t t = idx - 131072;
        int k = (int)t & 511, mrow = (int)(t >> 9);
        float v = (k < 256) ? E0[mrow * 256 + k] : -E0[262144 + mrow * 256 + (k - 256)];
        splitw(v, h, l); g_Eh[t] = h; g_El[t] = l;
    } else {                                      // D [512][1024]
        size_t t = idx - 131072 - 524288;
        int mrow = (int)t & 1023, j = (int)(t >> 10);
        float v = (j < 256) ? E0[mrow * 256 + j] : -E0[262144 + mrow * 256 + (j - 256)];
        splitw(v, h, l); g_Dh[t] = h; g_Dl[t] = l;
    }
}

__global__ void k_x1(const float* __restrict__ gammas) {
    int idx = blockIdx.x * 256 + threadIdx.x;          // 8192*512
    g_x[idx] = gammas[1] * g_b0[idx];
}

__global__ void k_final(float* __restrict__ out) {
    int idx = blockIdx.x * 256 + threadIdx.x;          // 2*8192*256
    int k = idx & 255, b = (idx >> 8) & 8191, cch = idx >> 21;
    out[idx] = g_xmap[(size_t)b * 512 + cch * 256 + k];
}

__global__ void k_scalars(float* __restrict__ out) {
    if (threadIdx.x == 0 && blockIdx.x == 0) {
        size_t base = 2ull * BB * KD;
        out[base + 0] = g_acc[0] / (float)BB;
        out[base + 1] = g_acc[1] / ((float)2 * KD * BB * TT);
        out[base + 2] = g_acc[2] / (float)BB;
    }
}

// ---------------- launch ----------------
extern "C" void kernel_launch(void* const* d_in, const int* in_sizes, int n_in,
                              void* d_out, int out_size) {
    const float* y      = (const float*)d_in[0];
    const float* W      = (const float*)d_in[1];
    const float* WX     = (const float*)d_in[2];
    const float* E0     = (const float*)d_in[3];
    const float* etas   = (const float*)d_in[4];
    const float* gammas = (const float*)d_in[5];
    float* out = (float*)d_out;

    void *p;
    cudaGetSymbolAddress(&p, g_Rh);   const float* fRh = (const float*)p;
    cudaGetSymbolAddress(&p, g_Rl);   const float* fRl = (const float*)p;
    cudaGetSymbolAddress(&p, g_Wh);   const float* fWh = (const float*)p;
    cudaGetSymbolAddress(&p, g_Wl);   const float* fWl = (const float*)p;
    cudaGetSymbolAddress(&p, g_Eh);   const float* fEh = (const float*)p;
    cudaGetSymbolAddress(&p, g_El);   const float* fEl = (const float*)p;
    cudaGetSymbolAddress(&p, g_Dh);   const float* fDh = (const float*)p;
    cudaGetSymbolAddress(&p, g_Dl);   const float* fDl = (const float*)p;
    cudaGetSymbolAddress(&p, g_x);    float* fX   = (float*)p;
    cudaGetSymbolAddress(&p, g_xmap); float* fXm  = (float*)p;
    cudaGetSymbolAddress(&p, g_b0);   float* fB0  = (float*)p;
    cudaGetSymbolAddress(&p, g_xsp);  float* fXsp = (float*)p;

    cudaFuncSetAttribute(k_gemm<256, 512, 0>, cudaFuncAttributeMaxDynamicSharedMemorySize, SMEM_BYTES);
    cudaFuncSetAttribute(k_gemm<512, 512, 1>, cudaFuncAttributeMaxDynamicSharedMemorySize, SMEM_BYTES);
    cudaFuncSetAttribute(k_gemm<512, 1024, 2>, cudaFuncAttributeMaxDynamicSharedMemorySize, SMEM_BYTES);
    cudaFuncSetAttribute(k_gemm<1024, 512, 3>, cudaFuncAttributeMaxDynamicSharedMemorySize, SMEM_BYTES);

    k_zero<<<1, 32>>>();
    k_prep_R<<<dim3(16, 16), dim3(16, 16)>>>(W, WX);
    k_prepB<<<(131072 + 2 * 524288) / 256, 256>>>(E0, WX);

    // b0 = WXr . y  -> g_b0 [b][512]   (y is [b][2N] = [b][256] row-major, used raw as X)
    k_gemm<256, 512, 0><<<dim3(BB / 128, 4), 256, SMEM_BYTES>>>(fWh, fWl, y, fB0,
        nullptr, nullptr, nullptr, 0);
    k_x1<<<BB * 512 / 256, 256>>>(gammas);

    for (int i = 1; i <= TT; i++) {
        if (i > 1)
            k_gemm<512, 512, 1><<<dim3(BB / 128, 4), 256, SMEM_BYTES>>>(fRh, fRl, fXm, fX,
                fXm, fB0, gammas + i, 0);
        k_gemm<512, 1024, 2><<<dim3(BB / 128, 8), 256, SMEM_BYTES>>>(fEh, fEl, fX, fXsp,
            nullptr, nullptr, etas + i, (i == TT) ? 1 : 0);
        k_gemm<1024, 512, 3><<<dim3(BB / 128, 4), 256, SMEM_BYTES>>>(fDh, fDl, fXsp, fXm,
            fX, nullptr, nullptr, 0);
    }
    k_final<<<2 * BB * KD / 256, 256>>>(out);
    k_scalars<<<1, 32>>>(out);
}